// round 5
// baseline (speedup 1.0000x reference)
#include <cuda_runtime.h>
#include <cuda_bf16.h>
#include <math.h>

#define NN 100000
#define EE 1600000
#define FIN 128
#define FOUT 32
#define ALPHA 0.2f

#define SCAN_CH 512
#define SCAN_BLOCKS ((NN + SCAN_CH - 1) / SCAN_CH)   // 196

// Scratch (__device__ globals; no cudaMalloc allowed)
__device__ __align__(16) float g_Wx[(size_t)NN * FOUT];   // 12.8 MB
__device__ float g_as[NN];
__device__ float g_ad[NN];
__device__ float g_s[NN];                   // softmax denominator per node
__device__ int   g_cnt[NN];
__device__ int   g_rowptr[NN + 1];
__device__ int   g_wpos[NN];
__device__ int   g_bsum[SCAN_BLOCKS];
__device__ int   g_boff[SCAN_BLOCKS];
__device__ int   g_edst[EE];
__device__ float g_ev[EE];                  // exp(leaky(score)) per CSR slot

__device__ __forceinline__ float leaky(float v) {
    return v >= 0.0f ? v : ALPHA * v;
}

// ---------------------------------------------------------------------------
// K1: Wx = x @ W (one warp per row) + alpha projections + zero counters
// ---------------------------------------------------------------------------
__global__ __launch_bounds__(256) void k_gemm_alpha(
    const float* __restrict__ x, const float* __restrict__ W,
    const float* __restrict__ a, int n)
{
    // fold counter init into this kernel (grid covers >= n threads)
    int gtid = blockIdx.x * 256 + threadIdx.x;
    if (gtid < n) { g_cnt[gtid] = 0; g_s[gtid] = 0.0f; }

    __shared__ float Ws[FIN * FOUT];   // 16 KB
    for (int i = threadIdx.x; i < FIN * FOUT; i += blockDim.x) Ws[i] = W[i];
    __syncthreads();

    int warp = threadIdx.x >> 5;
    int lane = threadIdx.x & 31;
    int row = blockIdx.x * 8 + warp;
    if (row >= n) return;

    const float* xr = x + (size_t)row * FIN;
    float x0 = xr[lane];
    float x1 = xr[32 + lane];
    float x2 = xr[64 + lane];
    float x3 = xr[96 + lane];

    float acc = 0.0f;
#pragma unroll
    for (int k = 0; k < 32; k++)
        acc = fmaf(__shfl_sync(0xFFFFFFFFu, x0, k), Ws[k * FOUT + lane], acc);
#pragma unroll
    for (int k = 0; k < 32; k++)
        acc = fmaf(__shfl_sync(0xFFFFFFFFu, x1, k), Ws[(32 + k) * FOUT + lane], acc);
#pragma unroll
    for (int k = 0; k < 32; k++)
        acc = fmaf(__shfl_sync(0xFFFFFFFFu, x2, k), Ws[(64 + k) * FOUT + lane], acc);
#pragma unroll
    for (int k = 0; k < 32; k++)
        acc = fmaf(__shfl_sync(0xFFFFFFFFu, x3, k), Ws[(96 + k) * FOUT + lane], acc);

    g_Wx[(size_t)row * FOUT + lane] = acc;

    float vs = acc * a[lane];
    float vd = acc * a[FOUT + lane];
#pragma unroll
    for (int o = 16; o > 0; o >>= 1) {
        vs += __shfl_xor_sync(0xFFFFFFFFu, vs, o);
        vd += __shfl_xor_sync(0xFFFFFFFFu, vd, o);
    }
    if (lane == 0) {
        g_as[row] = vs;
        g_ad[row] = vd;
    }
}

// ---------------------------------------------------------------------------
// K2: histogram of src
// ---------------------------------------------------------------------------
__global__ __launch_bounds__(256) void k_hist(const int* __restrict__ ei, int E) {
    int e = blockIdx.x * blockDim.x + threadIdx.x;
    if (e >= E) return;
    atomicAdd(&g_cnt[ei[e]], 1);
}

// ---------------------------------------------------------------------------
// K3a/b/c: two-level exclusive scan of g_cnt -> g_rowptr (and g_wpos copy)
// ---------------------------------------------------------------------------
__global__ __launch_bounds__(SCAN_CH) void k_scan1(int n) {
    __shared__ int sm[SCAN_CH];
    int idx = blockIdx.x * SCAN_CH + threadIdx.x;
    sm[threadIdx.x] = (idx < n) ? g_cnt[idx] : 0;
    __syncthreads();
    for (int off = SCAN_CH / 2; off > 0; off >>= 1) {
        if (threadIdx.x < off) sm[threadIdx.x] += sm[threadIdx.x + off];
        __syncthreads();
    }
    if (threadIdx.x == 0) g_bsum[blockIdx.x] = sm[0];
}

__global__ __launch_bounds__(256) void k_scan2(int nb, int n, int E) {
    __shared__ int sm[256];
    int tid = threadIdx.x;
    int v = (tid < nb) ? g_bsum[tid] : 0;
    sm[tid] = v;
    __syncthreads();
    for (int off = 1; off < 256; off <<= 1) {
        int t = (tid >= off) ? sm[tid - off] : 0;
        __syncthreads();
        sm[tid] += t;
        __syncthreads();
    }
    if (tid < nb) g_boff[tid] = sm[tid] - v;   // exclusive
    if (tid == 0) g_rowptr[n] = E;
}

__global__ __launch_bounds__(SCAN_CH) void k_scan3(int n) {
    __shared__ int sm[SCAN_CH];
    int tid = threadIdx.x;
    int idx = blockIdx.x * SCAN_CH + tid;
    int v = (idx < n) ? g_cnt[idx] : 0;
    sm[tid] = v;
    __syncthreads();
    for (int off = 1; off < SCAN_CH; off <<= 1) {
        int t = (tid >= off) ? sm[tid - off] : 0;
        __syncthreads();
        sm[tid] += t;
        __syncthreads();
    }
    if (idx < n) {
        int ex = g_boff[blockIdx.x] + sm[tid] - v;   // exclusive scan value
        g_rowptr[idx] = ex;
        g_wpos[idx] = ex;
    }
}

// ---------------------------------------------------------------------------
// K4: scatter dst into CSR slots + compute ev per edge + denominator sum
// ---------------------------------------------------------------------------
__global__ __launch_bounds__(256) void k_scatter(const int* __restrict__ ei, int E) {
    int e = blockIdx.x * blockDim.x + threadIdx.x;
    if (e >= E) return;
    int s = ei[e];
    int d = ei[E + e];
    float ev = __expf(leaky(g_as[s] + g_ad[d]));
    int pos = atomicAdd(&g_wpos[s], 1);
    g_edst[pos] = d;
    g_ev[pos] = ev;
    atomicAdd(&g_s[s], ev);
}

// ---------------------------------------------------------------------------
// K5: aggregation + ELU. One warp per node; 8 edges in parallel per warp,
// 4 lanes per edge, each lane holds 2 float4s of the 32 features.
// 16 independent gathers in flight, single-level dependency d -> Wx[d].
// ---------------------------------------------------------------------------
__global__ __launch_bounds__(256) void k_agg(float* __restrict__ out, int n) {
    int u = (blockIdx.x * blockDim.x + threadIdx.x) >> 5;
    int lane = threadIdx.x & 31;
    if (u >= n) return;

    int beg = g_rowptr[u];
    int end = g_rowptr[u + 1];
    float4* op = reinterpret_cast<float4*>(out + (size_t)u * FOUT);

    if (beg == end) {            // isolated node: h = 0 -> elu(0) = 0
        if (lane < 8) op[lane] = make_float4(0.f, 0.f, 0.f, 0.f);
        return;
    }

    int sub = lane >> 2;         // edge subgroup 0..7
    int fl  = lane & 3;          // float4 slot 0..3 (this lane also does fl+4)

    float4 a0 = make_float4(0.f, 0.f, 0.f, 0.f);
    float4 a1 = make_float4(0.f, 0.f, 0.f, 0.f);
    const float4* Wx4 = reinterpret_cast<const float4*>(g_Wx);

    for (int i = beg + sub; i < end; i += 8) {
        int d = g_edst[i];                 // broadcast within 4-lane subgroup
        float ev = g_ev[i];
        const float4* wr = Wx4 + (size_t)d * 8;
        float4 w0 = wr[fl];
        float4 w1 = wr[fl + 4];
        a0.x = fmaf(ev, w0.x, a0.x); a0.y = fmaf(ev, w0.y, a0.y);
        a0.z = fmaf(ev, w0.z, a0.z); a0.w = fmaf(ev, w0.w, a0.w);
        a1.x = fmaf(ev, w1.x, a1.x); a1.y = fmaf(ev, w1.y, a1.y);
        a1.z = fmaf(ev, w1.z, a1.z); a1.w = fmaf(ev, w1.w, a1.w);
    }

    // combine the 8 subgroups (lanes sharing fl): xor 4, 8, 16
#pragma unroll
    for (int o = 4; o <= 16; o <<= 1) {
        a0.x += __shfl_xor_sync(0xFFFFFFFFu, a0.x, o);
        a0.y += __shfl_xor_sync(0xFFFFFFFFu, a0.y, o);
        a0.z += __shfl_xor_sync(0xFFFFFFFFu, a0.z, o);
        a0.w += __shfl_xor_sync(0xFFFFFFFFu, a0.w, o);
        a1.x += __shfl_xor_sync(0xFFFFFFFFu, a1.x, o);
        a1.y += __shfl_xor_sync(0xFFFFFFFFu, a1.y, o);
        a1.z += __shfl_xor_sync(0xFFFFFFFFu, a1.z, o);
        a1.w += __shfl_xor_sync(0xFFFFFFFFu, a1.w, o);
    }

    if (lane < 4) {
        float inv = 1.0f / g_s[u];
        float4 r0, r1;
        float v;
        v = a0.x * inv; r0.x = v > 0.f ? v : expm1f(v);
        v = a0.y * inv; r0.y = v > 0.f ? v : expm1f(v);
        v = a0.z * inv; r0.z = v > 0.f ? v : expm1f(v);
        v = a0.w * inv; r0.w = v > 0.f ? v : expm1f(v);
        v = a1.x * inv; r1.x = v > 0.f ? v : expm1f(v);
        v = a1.y * inv; r1.y = v > 0.f ? v : expm1f(v);
        v = a1.z * inv; r1.z = v > 0.f ? v : expm1f(v);
        v = a1.w * inv; r1.w = v > 0.f ? v : expm1f(v);
        op[fl] = r0;
        op[fl + 4] = r1;
    }
}

// ---------------------------------------------------------------------------
extern "C" void kernel_launch(void* const* d_in, const int* in_sizes, int n_in,
                              void* d_out, int out_size)
{
    const float* x  = (const float*)d_in[0];   // (N, 128)
    const float* W  = (const float*)d_in[1];   // (128, 32)
    const float* a  = (const float*)d_in[2];   // (64, 1)
    const int*   ei = (const int*)d_in[3];     // (2, E) int32
    float* out = (float*)d_out;                // (N, 32)

    const int n = in_sizes[0] / FIN;
    const int E = in_sizes[3] / 2;
    const int nb = (n + SCAN_CH - 1) / SCAN_CH;

    k_gemm_alpha<<<(n + 7) / 8, 256>>>(x, W, a, n);
    k_hist<<<(E + 255) / 256, 256>>>(ei, E);
    k_scan1<<<nb, SCAN_CH>>>(n);
    k_scan2<<<1, 256>>>(nb, n, E);
    k_scan3<<<nb, SCAN_CH>>>(n);
    k_scatter<<<(E + 255) / 256, 256>>>(ei, E);
    k_agg<<<(n * 32 + 255) / 256, 256>>>(out, n);
}